// round 5
// baseline (speedup 1.0000x reference)
#include <cuda_runtime.h>
#include <cuda_fp16.h>

// MedianFilterLoss, decomposed:
//   loss = sum_i softplus((1-2*t_i)*x_i)                       (base, elementwise)
//        - sum_{runs of ones, len>=3} max-weight subset of w_i = relu(-x_i)
//          with pairwise distance >= 3 (3-state max-plus DP per run)
// One block per row (TILE = T_LEN): no cross-tile runs, all DP traffic in smem.
// Shared encoding: one half per element, = relu(-x) if t==1, else -1.0.
// Phase 2: convergent predicated 64-step DP per thread; prefix runs skipped via
// inPref; suffix runs walked by owner inside the tile (row ends close the run).

#define T_LEN 16384
#define NTH   256
#define EPT   64          // elements per thread
#define ROWH  72          // halves per thread-row (64 data + 8 pad) = 144B

__device__ float g_partial[2048];
__device__ unsigned int g_done;

__global__ void __launch_bounds__(NTH) mfl_fused(const float* __restrict__ xg,
                                                 const int* __restrict__ tg,
                                                 float* __restrict__ o,
                                                 double inv_n) {
    __shared__ __half sw[NTH * ROWH];
    __shared__ float wsum[NTH / 32];
    __shared__ double sdbl[NTH];
    __shared__ unsigned int s_last;

    const int bid  = blockIdx.x;
    const int base = bid * T_LEN;
    const int tid  = threadIdx.x;
    const int lane = tid & 31;
    const int wid  = tid >> 5;

    // ---- Phase 1: coalesced load; fp32 base loss; stage sign-encoded w ----
    float accA = 0.0f, accB = 0.0f;
    const float4* xv = reinterpret_cast<const float4*>(xg + base);
    const int4*   tv = reinterpret_cast<const int4*>(tg + base);
#pragma unroll
    for (int k = 0; k < T_LEN / 4 / NTH; ++k) {       // 16 iters
        int i = k * NTH + tid;
        float4 v  = xv[i];
        int4   t4 = tv[i];
        float xs[4] = {v.x, v.y, v.z, v.w};
        int   ts[4] = {t4.x, t4.y, t4.z, t4.w};
        float enc[4];
#pragma unroll
        for (int j = 0; j < 4; ++j) {
            float x  = xs[j];
            bool one = (ts[j] != 0);
            float L  = __logf(1.0f + __expf(-fabsf(x)));   // target-independent
            float s  = one ? -x : x;
            float r  = fmaxf(s, 0.0f);                     // relu of signed logit
            if (j & 1) accB += r + L; else accA += r + L;
            enc[j] = one ? r : -1.0f;                      // w if one, else sentinel
        }
        __half2 h0 = __floats2half2_rn(enc[0], enc[1]);
        __half2 h1 = __floats2half2_rn(enc[2], enc[3]);
        // group i covers elements 4i..4i+3 -> thread-row i>>4, col (i&15)*4
        unsigned r = (unsigned)(i >> 4);
        unsigned c = (unsigned)(i & 15) * 4u;
        uint2 pk;
        pk.x = *reinterpret_cast<unsigned int*>(&h0);
        pk.y = *reinterpret_cast<unsigned int*>(&h1);
        *reinterpret_cast<uint2*>(&sw[r * ROWH + c]) = pk;
    }
    float acc = accA + accB;
    __syncthreads();

    // ---- Phase 2: convergent per-thread DP over 64 contiguous elements ----
    bool inPref = (tid == 0) ? false
                             : (__half2float(sw[(tid - 1) * ROWH + (EPT - 1)]) >= 0.0f);

    float m0 = 0.0f, m1 = 0.0f, m2 = 0.0f;
    int len = 0;
    const unsigned bh = (unsigned)tid * ROWH;
#pragma unroll
    for (int c = 0; c < EPT / 8; ++c) {               // 8 x LDS.128
        uint4 q = *reinterpret_cast<const uint4*>(&sw[bh + c * 8]);
        unsigned ws[4] = {q.x, q.y, q.z, q.w};
#pragma unroll
        for (int u = 0; u < 4; ++u) {
            __half2 hh = *reinterpret_cast<__half2*>(&ws[u]);
            float2 f2 = __half22float2(hh);
            float fv[2] = {f2.x, f2.y};
#pragma unroll
            for (int e = 0; e < 2; ++e) {
                float f = fv[e];
                bool b = (f >= 0.0f);
                inPref = inPref && b;
                bool bb = b && !inPref;
                float nm2 = fmaxf(m2, m0 + f);
                if (!bb && len >= 3) acc -= m2;       // close local run
                m0 = bb ? m1 : 0.0f;
                m1 = bb ? m2 : 0.0f;
                m2 = bb ? nm2 : 0.0f;
                len = bb ? len + 1 : 0;
            }
        }
    }

    // ---- suffix run: owner walks forward inside the tile (rare, short) ----
    if (len > 0) {
        int p = (tid + 1) * EPT;
        while (p < T_LEN) {
            float v = __half2float(sw[(p >> 6) * ROWH + (p & 63)]);
            if (v < 0.0f) break;
            float nm = fmaxf(m2, m0 + v);
            m0 = m1; m1 = m2; m2 = nm; ++len; ++p;
        }
        if (len >= 3) acc -= m2;
    }

    // ---- block reduction ----
#pragma unroll
    for (int off = 16; off; off >>= 1)
        acc += __shfl_down_sync(0xFFFFFFFFu, acc, off);
    if (lane == 0) wsum[wid] = acc;
    __syncthreads();
    float blocksum = 0.0f;
    if (wid == 0) {
        float v = (lane < NTH / 32) ? wsum[lane] : 0.0f;
#pragma unroll
        for (int off = 4; off; off >>= 1)
            v += __shfl_down_sync(0xFFFFFFFFu, v, off);
        blocksum = v;
    }

    // ---- last-block-done final reduction (single launch) ----
    if (tid == 0) {
        g_partial[bid] = blocksum;
        __threadfence();
        unsigned old = atomicAdd(&g_done, 1u);
        s_last = (old == gridDim.x - 1) ? 1u : 0u;
    }
    __syncthreads();
    if (s_last) {
        const volatile float* gp = g_partial;
        double sv = 0.0;
        for (int i = tid; i < (int)gridDim.x; i += NTH)
            sv += (double)gp[i];
        sdbl[tid] = sv;
        __syncthreads();
#pragma unroll
        for (int off = NTH / 2; off; off >>= 1) {
            if (tid < off) sdbl[tid] += sdbl[tid + off];
            __syncthreads();
        }
        if (tid == 0) {
            o[0] = (float)(sdbl[0] * inv_n);
            g_done = 0;                               // reset for next graph replay
        }
    }
}

extern "C" void kernel_launch(void* const* d_in, const int* in_sizes, int n_in,
                              void* d_out, int out_size) {
    const float* xg = (const float*)d_in[0];
    const int*   tg = (const int*)d_in[1];
    long long n = (long long)in_sizes[0];      // 1024 * 16384
    int grid = (int)(n / T_LEN);               // 1024
    mfl_fused<<<grid, NTH>>>(xg, tg, (float*)d_out, 1.0 / (double)n);
}

// round 6
// speedup vs baseline: 1.1031x; 1.1031x over previous
#include <cuda_runtime.h>
#include <cuda_fp16.h>

// MedianFilterLoss, decomposed:
//   loss = sum_i softplus((1-2*t_i)*x_i)                       (base, elementwise)
//        - sum_{runs of ones, len>=3} max-weight subset of w_i = relu(-x_i)
//          with pairwise distance >= 3 (3-state max-plus DP per run)
// Shared encoding: one half per element, = relu(-x) if t==1, else -1.0.
// Phase 2: convergent predicated 32-step DP per thread + 8-step register overlap
// into the neighbor's chunk; serial walk only for runs alive past the overlap.

#define T_LEN 16384
#define TILE  8192
#define NTH   256
#define EPT   32
#define ROWH  40          // halves per thread-row (32 data + 8 pad) = 80B

__device__ float g_partial[2048];
__device__ unsigned int g_done;

__global__ void __launch_bounds__(NTH, 5) mfl_fused(const float* __restrict__ xg,
                                                    const int* __restrict__ tg,
                                                    float* __restrict__ o,
                                                    double inv_n) {
    __shared__ __half sw[NTH * ROWH];
    __shared__ float wsum[NTH / 32];
    __shared__ double sdbl[NTH];
    __shared__ unsigned int s_last;

    const int bid  = blockIdx.x;
    const int row  = bid >> 1;
    const int half = bid & 1;
    const int base = row * T_LEN + half * TILE;
    const int tid  = threadIdx.x;
    const int lane = tid & 31;
    const int wid  = tid >> 5;

    // ---- Phase 1: macro-batched coalesced loads (MLP~8); fp32 base loss ----
    float accA = 0.0f, accB = 0.0f;
    const float4* xv = reinterpret_cast<const float4*>(xg + base);
    const int4*   tv = reinterpret_cast<const int4*>(tg + base);
#pragma unroll
    for (int mb = 0; mb < 2; ++mb) {
        float4 vx[4];
        int4   vt[4];
#pragma unroll
        for (int q = 0; q < 4; ++q) {
            int i = (mb * 4 + q) * NTH + tid;
            vx[q] = xv[i];
            vt[q] = tv[i];
        }
#pragma unroll
        for (int q = 0; q < 4; ++q) {
            int i = (mb * 4 + q) * NTH + tid;
            float xs[4] = {vx[q].x, vx[q].y, vx[q].z, vx[q].w};
            int   ts[4] = {vt[q].x, vt[q].y, vt[q].z, vt[q].w};
            float enc[4];
#pragma unroll
            for (int j = 0; j < 4; ++j) {
                float x  = xs[j];
                bool one = (ts[j] != 0);
                float L  = __logf(1.0f + __expf(-fabsf(x)));
                float s  = one ? -x : x;
                float r  = fmaxf(s, 0.0f);
                if (j & 1) accB += r + L; else accA += r + L;
                enc[j] = one ? r : -1.0f;
            }
            __half2 h0 = __floats2half2_rn(enc[0], enc[1]);
            __half2 h1 = __floats2half2_rn(enc[2], enc[3]);
            unsigned r2 = (unsigned)(i >> 3);
            unsigned c2 = (unsigned)(i & 7) * 4u;
            uint2 pk;
            pk.x = *reinterpret_cast<unsigned int*>(&h0);
            pk.y = *reinterpret_cast<unsigned int*>(&h1);
            *reinterpret_cast<uint2*>(&sw[r2 * ROWH + c2]) = pk;
        }
    }
    float acc = accA + accB;
    __syncthreads();

    // ---- Phase 2: convergent per-thread DP over 32 contiguous elements ----
    bool inPref;
    if (tid == 0) inPref = half ? (tg[base - 1] != 0) : false;
    else          inPref = (__half2float(sw[(tid - 1) * ROWH + (EPT - 1)]) >= 0.0f);

    float m0 = 0.0f, m1 = 0.0f, m2 = 0.0f;
    int len = 0;
    const unsigned bh = (unsigned)tid * ROWH;
#pragma unroll
    for (int c = 0; c < EPT / 8; ++c) {               // 4 x LDS.128
        uint4 q = *reinterpret_cast<const uint4*>(&sw[bh + c * 8]);
        unsigned ws[4] = {q.x, q.y, q.z, q.w};
#pragma unroll
        for (int u = 0; u < 4; ++u) {
            __half2 hh = *reinterpret_cast<__half2*>(&ws[u]);
            float2 f2 = __half22float2(hh);
            float fv[2] = {f2.x, f2.y};
#pragma unroll
            for (int e = 0; e < 2; ++e) {
                float f = fv[e];
                bool b = (f >= 0.0f);
                inPref = inPref && b;
                bool bb = b && !inPref;
                float nm2 = fmaxf(m2, m0 + f);
                if (!bb && len >= 3) acc -= m2;       // close local run
                m0 = bb ? m1 : 0.0f;
                m1 = bb ? m2 : 0.0f;
                m2 = bb ? nm2 : 0.0f;
                len = bb ? len + 1 : 0;
            }
        }
    }

    // ---- suffix run: 8-step register overlap into neighbor, rare serial tail ----
    if (len > 0) {
        int p = (tid + 1) * EPT;
        bool alive = true;
        if (tid < NTH - 1) {
            uint4 q = *reinterpret_cast<const uint4*>(&sw[(tid + 1) * ROWH]);
            unsigned ws[4] = {q.x, q.y, q.z, q.w};
#pragma unroll
            for (int u = 0; u < 4; ++u) {
                __half2 hh = *reinterpret_cast<__half2*>(&ws[u]);
                float2 f2 = __half22float2(hh);
                float fv[2] = {f2.x, f2.y};
#pragma unroll
                for (int e = 0; e < 2; ++e) {
                    float f = fv[e];
                    bool cont = alive && (f >= 0.0f);
                    if (alive && !cont && len >= 3) acc -= m2;   // run closes here
                    float nm2 = fmaxf(m2, m0 + f);
                    m0 = cont ? m1 : m0;
                    m1 = cont ? m2 : m1;
                    m2 = cont ? nm2 : m2;
                    len += cont ? 1 : 0;
                    alive = cont;
                }
            }
            p += 8;
        }
        if (alive) {                                   // run still open (rare)
            while (p < TILE) {
                float v = __half2float(sw[(p >> 5) * ROWH + (p & 31)]);
                if (v < 0.0f) break;
                float nm = fmaxf(m2, m0 + v);
                m0 = m1; m1 = m2; m2 = nm; ++len; ++p;
            }
            if (p == TILE && half == 0) {              // spill across mid-row boundary
                int g = base + TILE;
                const int gend = row * T_LEN + T_LEN;
                while (g < gend && tg[g] != 0) {
                    float w = fmaxf(-xg[g], 0.0f);
                    float nm = fmaxf(m2, m0 + w);
                    m0 = m1; m1 = m2; m2 = nm; ++len; ++g;
                }
            }
            if (len >= 3) acc -= m2;
        }
    }

    // ---- block reduction ----
#pragma unroll
    for (int off = 16; off; off >>= 1)
        acc += __shfl_down_sync(0xFFFFFFFFu, acc, off);
    if (lane == 0) wsum[wid] = acc;
    __syncthreads();
    float blocksum = 0.0f;
    if (wid == 0) {
        float v = (lane < NTH / 32) ? wsum[lane] : 0.0f;
#pragma unroll
        for (int off = 4; off; off >>= 1)
            v += __shfl_down_sync(0xFFFFFFFFu, v, off);
        blocksum = v;
    }

    // ---- last-block-done final reduction (single launch) ----
    if (tid == 0) {
        g_partial[bid] = blocksum;
        __threadfence();
        unsigned old = atomicAdd(&g_done, 1u);
        s_last = (old == gridDim.x - 1) ? 1u : 0u;
    }
    __syncthreads();
    if (s_last) {
        const volatile float* gp = g_partial;
        double sv = 0.0;
        for (int i = tid; i < (int)gridDim.x; i += NTH)
            sv += (double)gp[i];
        sdbl[tid] = sv;
        __syncthreads();
#pragma unroll
        for (int off = NTH / 2; off; off >>= 1) {
            if (tid < off) sdbl[tid] += sdbl[tid + off];
            __syncthreads();
        }
        if (tid == 0) {
            o[0] = (float)(sdbl[0] * inv_n);
            g_done = 0;                               // reset for next graph replay
        }
    }
}

extern "C" void kernel_launch(void* const* d_in, const int* in_sizes, int n_in,
                              void* d_out, int out_size) {
    const float* xg = (const float*)d_in[0];
    const int*   tg = (const int*)d_in[1];
    long long n = (long long)in_sizes[0];      // 1024 * 16384
    int grid = (int)(n / TILE);                // 2048
    mfl_fused<<<grid, NTH>>>(xg, tg, (float*)d_out, 1.0 / (double)n);
}

// round 9
// speedup vs baseline: 1.1126x; 1.0087x over previous
#include <cuda_runtime.h>

// MedianFilterLoss, decomposed:
//   loss = sum_i softplus((1-2*t_i)*x_i)                       (base, elementwise)
//        - sum_{runs of ones, len>=3} max-weight subset of w_i = relu(-x_i)
//          with pairwise distance >= 3 (3-state max-plus DP per run)
// Float staging in smem: element = relu(-x) if t==1, else -1.0 sentinel.
// DP state reset = -0.0f; computed values forced +; "len>=3" == sign(m0)>=0.
// Prefix runs: computed but first close suppressed (owner = previous thread).

#define T_LEN 16384
#define TILE  8192
#define NTH   256
#define EPT   32
#define ROWF  36          // floats per thread-row (32 data + 4 pad) = 144B
#define NEGZ  __int_as_float(0x80000000)
#define LN2F  0.6931471805599453f

__device__ float g_partial[2048];
__device__ unsigned int g_done;

__global__ void __launch_bounds__(NTH, 5) mfl_fused(const float* __restrict__ xg,
                                                    const int* __restrict__ tg,
                                                    float* __restrict__ o,
                                                    double inv_n) {
    __shared__ float swf[NTH * ROWF];
    __shared__ float wsum[NTH / 32];
    __shared__ double sdbl[NTH];
    __shared__ unsigned int s_last;

    const int bid  = blockIdx.x;
    const int row  = bid >> 1;
    const int half = bid & 1;
    const int base = row * T_LEN + half * TILE;
    const int tid  = threadIdx.x;
    const int lane = tid & 31;
    const int wid  = tid >> 5;

    // ---- Phase 1: macro-batched coalesced loads; base loss; float staging ----
    float accR = 0.0f;    // relu terms (+ DP corrections later)
    float accL = 0.0f;    // log2 terms, scaled by ln2 at the end
    const float4* xv = reinterpret_cast<const float4*>(xg + base);
    const int4*   tv = reinterpret_cast<const int4*>(tg + base);
#pragma unroll
    for (int mb = 0; mb < 2; ++mb) {
        float4 vx[4];
        int4   vt[4];
#pragma unroll
        for (int q = 0; q < 4; ++q) {
            int i = (mb * 4 + q) * NTH + tid;
            vx[q] = xv[i];
            vt[q] = tv[i];
        }
#pragma unroll
        for (int q = 0; q < 4; ++q) {
            int i = (mb * 4 + q) * NTH + tid;
            float xs[4] = {vx[q].x, vx[q].y, vx[q].z, vx[q].w};
            int   ts[4] = {vt[q].x, vt[q].y, vt[q].z, vt[q].w};
            float enc[4];
#pragma unroll
            for (int j = 0; j < 4; ++j) {
                float x  = xs[j];
                bool one = (ts[j] != 0);
                // log2(1 + exp2(-|x|*log2e)); * ln2 deferred to the end
                float u  = exp2f(fabsf(x) * -1.4426950408889634f);
                accL    += __log2f(1.0f + u);
                float s  = one ? -x : x;
                float w  = fmaxf(s, 0.0f);
                accR    += w;
                enc[j]   = one ? w : -1.0f;
            }
            unsigned r2 = (unsigned)(i >> 3);
            unsigned c2 = (unsigned)(i & 7) * 4u;
            float4 st = {enc[0], enc[1], enc[2], enc[3]};
            *reinterpret_cast<float4*>(&swf[r2 * ROWF + c2]) = st;
        }
    }
    float acc = accR;     // corrections subtract from here; accL folded at end
    __syncthreads();

    // ---- Phase 2: convergent per-thread DP over 32 contiguous elements ----
    bool suppress;
    if (tid == 0) suppress = half ? (tg[base - 1] != 0) : false;
    else          suppress = (swf[(tid - 1) * ROWF + (EPT - 1)] >= 0.0f);

    float m0 = NEGZ, m1 = NEGZ, m2 = NEGZ;
    bool b = false;
    const float* mine = &swf[tid * ROWF];
#pragma unroll
    for (int c = 0; c < EPT / 4; ++c) {               // 8 x LDS.128
        float4 q = *reinterpret_cast<const float4*>(mine + c * 4);
        float fv[4] = {q.x, q.y, q.z, q.w};
#pragma unroll
        for (int e = 0; e < 4; ++e) {
            float f = fv[e];
            b = (f >= 0.0f);
            bool doclose = !b && !suppress && (__float_as_int(m0) >= 0);
            if (doclose) acc -= m2;
            suppress = suppress && b;
            float nm2 = fabsf(fmaxf(m2, m0 + f));
            m0 = b ? m1 : NEGZ;
            m1 = b ? m2 : NEGZ;
            m2 = b ? nm2 : NEGZ;
        }
    }

    // ---- suffix: run open at chunk end -> 8-elem register overlap + rare walk ----
    if (b && !suppress) {
        bool alive = true;
        if (tid < NTH - 1) {
            const float* nb = &swf[(tid + 1) * ROWF];
#pragma unroll
            for (int c = 0; c < 2; ++c) {
                float4 q = *reinterpret_cast<const float4*>(nb + c * 4);
                float fv[4] = {q.x, q.y, q.z, q.w};
#pragma unroll
                for (int e = 0; e < 4; ++e) {
                    float f = fv[e];
                    bool cont = alive && (f >= 0.0f);
                    bool cls  = alive && !cont && (__float_as_int(m0) >= 0);
                    if (cls) acc -= m2;
                    float nm2 = fabsf(fmaxf(m2, m0 + f));
                    m0 = cont ? m1 : m0;
                    m1 = cont ? m2 : m1;
                    m2 = cont ? nm2 : m2;
                    alive = cont;
                }
            }
        }
        if (alive) {                                   // rare: run alive past +8
            int p = (tid + 1) * EPT + ((tid < NTH - 1) ? 8 : 0);
            while (p < TILE) {
                float f = swf[(p >> 5) * ROWF + (p & 31)];
                if (f < 0.0f) break;
                float nm2 = fabsf(fmaxf(m2, m0 + f));
                m0 = m1; m1 = m2; m2 = nm2; ++p;
            }
            if (p == TILE && half == 0) {              // spill across mid-row boundary
                int g = base + TILE;
                const int gend = row * T_LEN + T_LEN;
                while (g < gend && tg[g] != 0) {
                    float w = fmaxf(-xg[g], 0.0f);
                    float nm2 = fabsf(fmaxf(m2, m0 + w));
                    m0 = m1; m1 = m2; m2 = nm2; ++g;
                }
            }
            if (__float_as_int(m0) >= 0) acc -= m2;    // close at zero / row end
        }
    }

    acc = fmaf(accL, LN2F, acc);

    // ---- block reduction ----
#pragma unroll
    for (int off = 16; off; off >>= 1)
        acc += __shfl_down_sync(0xFFFFFFFFu, acc, off);
    if (lane == 0) wsum[wid] = acc;
    __syncthreads();
    float blocksum = 0.0f;
    if (wid == 0) {
        float v = (lane < NTH / 32) ? wsum[lane] : 0.0f;
#pragma unroll
        for (int off = 4; off; off >>= 1)
            v += __shfl_down_sync(0xFFFFFFFFu, v, off);
        blocksum = v;
    }

    // ---- last-block-done final reduction (single launch) ----
    if (tid == 0) {
        g_partial[bid] = blocksum;
        __threadfence();
        unsigned old = atomicAdd(&g_done, 1u);
        s_last = (old == gridDim.x - 1) ? 1u : 0u;
    }
    __syncthreads();
    if (s_last) {
        const volatile float* gp = g_partial;
        double sv = 0.0;
        for (int i = tid; i < (int)gridDim.x; i += NTH)
            sv += (double)gp[i];
        sdbl[tid] = sv;
        __syncthreads();
#pragma unroll
        for (int off = NTH / 2; off; off >>= 1) {
            if (tid < off) sdbl[tid] += sdbl[tid + off];
            __syncthreads();
        }
        if (tid == 0) {
            o[0] = (float)(sdbl[0] * inv_n);
            g_done = 0;                               // reset for next graph replay
        }
    }
}

extern "C" void kernel_launch(void* const* d_in, const int* in_sizes, int n_in,
                              void* d_out, int out_size) {
    const float* xg = (const float*)d_in[0];
    const int*   tg = (const int*)d_in[1];
    long long n = (long long)in_sizes[0];      // 1024 * 16384
    int grid = (int)(n / TILE);                // 2048
    mfl_fused<<<grid, NTH>>>(xg, tg, (float*)d_out, 1.0 / (double)n);
}